// round 6
// baseline (speedup 1.0000x reference)
#include <cuda_runtime.h>
#include <cstdint>

#define NSIDE 128
#define NPIX (12*NSIDE*NSIDE)   /* 196608 */
#define B 8
#define CIN 16
#define COUT 32
#define BC (B*CIN)              /* 128 */
#define TILE_P 32
#define CSTRIDE 132             /* 128 floats per pixel-chunk row + 4 pad (528B, 16B-mult) */
#define WS_FLOATS 4608
#define VB_FLOATS (2*TILE_P*CSTRIDE)          /* 8448 */
/* smem: weights + 2 chunk buffers + neigh table + 2 mbarriers (16B-aligned) */
#define NS_INTS (TILE_P*9)                    /* 288 */
#define SMEM_BYTES ((WS_FLOATS + VB_FLOATS)*4 + NS_INTS*4 + 32)

// scratch: transposed, zero-padded x  (pixel-major: xt[idx][c*8+b])
__device__ float g_xt[(NPIX + 1) * BC];

// ---------------------------------------------------------------------------
// Kernel A: transpose x [B][CIN][NPIX] -> xt [NPIX+1][c*8+b], row NPIX = zeros
// ---------------------------------------------------------------------------
__global__ void transpose_kernel(const float* __restrict__ x) {
    __shared__ float tile[BC * 33];
    const int tid  = threadIdx.x;
    const int idx0 = blockIdx.x * 32;

    #pragma unroll
    for (int i = tid; i < BC * 32; i += 256) {
        int r  = i >> 5;            // r = b*16 + c
        int j  = i & 31;
        int cc = (r & 15) * 8 + (r >> 4);
        tile[cc * 33 + j] = x[r * NPIX + idx0 + j];
    }
    __syncthreads();
    #pragma unroll
    for (int i = tid; i < BC * 32; i += 256) {
        int j  = i >> 7;
        int cc = i & 127;
        g_xt[(idx0 + j) * BC + cc] = tile[cc * 33 + j];
    }
    if (blockIdx.x == 0 && tid < BC) g_xt[NPIX * BC + tid] = 0.0f;
}

// ---------------------------------------------------------------------------
// PTX helpers
// ---------------------------------------------------------------------------
__device__ __forceinline__ unsigned long long ffma2(unsigned long long a,
                                                    unsigned long long b,
                                                    unsigned long long c) {
    unsigned long long d;
    asm("fma.rn.f32x2 %0, %1, %2, %3;" : "=l"(d) : "l"(a), "l"(b), "l"(c));
    return d;
}
__device__ __forceinline__ unsigned long long pack2(float x) {
    unsigned long long r;
    unsigned u = __float_as_uint(x);
    asm("mov.b64 %0, {%1, %1};" : "=l"(r) : "r"(u));
    return r;
}
__device__ __forceinline__ void mbar_init(uint32_t mbar, uint32_t count) {
    asm volatile("mbarrier.init.shared.b64 [%0], %1;" :: "r"(mbar), "r"(count) : "memory");
}
__device__ __forceinline__ void mbar_expect_tx(uint32_t mbar, uint32_t bytes) {
    asm volatile("mbarrier.arrive.expect_tx.shared.b64 _, [%0], %1;"
                 :: "r"(mbar), "r"(bytes) : "memory");
}
__device__ __forceinline__ void mbar_wait(uint32_t mbar, uint32_t parity) {
    asm volatile(
        "{\n\t"
        ".reg .pred P;\n\t"
        "WAIT_%=:\n\t"
        "mbarrier.try_wait.parity.acquire.cta.shared::cta.b64 P, [%0], %1, 0x989680;\n\t"
        "@!P bra WAIT_%=;\n\t"
        "}"
        :: "r"(mbar), "r"(parity) : "memory");
}
// one 512B bulk copy: gmem row -> smem row, completion counted on mbar
__device__ __forceinline__ void cp_bulk(uint32_t dst, const void* src,
                                        uint32_t bytes, uint32_t mbar) {
    asm volatile(
        "cp.async.bulk.shared::cta.global.mbarrier::complete_tx::bytes [%0], [%1], %2, [%3];"
        :: "r"(dst), "l"(src), "r"(bytes), "r"(mbar) : "memory");
}

// ---------------------------------------------------------------------------
// Kernel B: 32-pixel tiles, bulk-copy k-streamed double buffer, 2 CTAs/SM
//   thread tile = 8b x 4o  (256 thr = 32 lp x 8 og)
// ---------------------------------------------------------------------------
__global__ void __launch_bounds__(256, 2) conv_kernel(
    const float* __restrict__ weight,   // [COUT][CIN][9]
    const float* __restrict__ bias,     // [COUT]
    const int*   __restrict__ neigh,    // [NPIX][9]
    float*       __restrict__ out)      // [B][COUT][NPIX]
{
    extern __shared__ char smem[];
    float* wS = (float*)smem;                      // [9][16][32] = 4608 f
    float* vB = wS + WS_FLOATS;                    // [2][32][CSTRIDE]
    int*   nS = (int*)(vB + VB_FLOATS);            // [288]
    float* oS = vB;                                // reused after compute

    const int tid = threadIdx.x;
    const int p0  = blockIdx.x * TILE_P;

    const uint32_t smem_u32 = (uint32_t)__cvta_generic_to_shared(smem);
    const uint32_t vB_u32   = smem_u32 + WS_FLOATS * 4;
    // mbarriers: 16B-aligned slot right after nS
    const uint32_t mb_base  = (smem_u32 + (WS_FLOATS + VB_FLOATS) * 4
                               + NS_INTS * 4 + 15) & ~15u;

    // stage weights as wS[k][c][o]
    for (int i = tid; i < WS_FLOATS; i += 256) {
        int k = i >> 9, rem = i & 511, c = rem >> 5, o = rem & 31;
        wS[i] = weight[o * 144 + c * 9 + k];
    }
    for (int i = tid; i < NS_INTS; i += 256) nS[i] = neigh[p0 * 9 + i];
    if (tid == 0) { mbar_init(mb_base, 1); mbar_init(mb_base + 8, 1); }
    __syncthreads();

    // chunk loader: 32 neighbour rows x 512B via 32 bulk copies
    auto load_chunk = [&](int k, int buf) {
        if (tid == 0) mbar_expect_tx(mb_base + buf * 8, TILE_P * 512);
        if (tid < TILE_P) {
            int idx = nS[tid * 9 + k];
            uint32_t dst = vB_u32 + (uint32_t)(buf * TILE_P + tid) * (CSTRIDE * 4);
            cp_bulk(dst, g_xt + (size_t)idx * BC, 512, mb_base + buf * 8);
        }
    };

    load_chunk(0, 0);

    // compute mapping: thread (lp, og) -> pixel p0+lp, outputs og*4..og*4+3
    const int lp = tid >> 3;
    const int og = tid & 7;

    unsigned long long acc[4][4];
    #pragma unroll
    for (int j = 0; j < 4; j++)
        #pragma unroll
        for (int i = 0; i < 4; i++) acc[j][i] = 0ULL;

    const float4* w4 = (const float4*)wS;
    int ph0 = 0, ph1 = 0;

    for (int k = 0; k < 9; k++) {
        if (k + 1 < 9) load_chunk(k + 1, (k + 1) & 1);

        const int buf = k & 1;
        if (buf == 0) { mbar_wait(mb_base, ph0);     ph0 ^= 1; }
        else          { mbar_wait(mb_base + 8, ph1); ph1 ^= 1; }

        const ulonglong2* v2 =
            (const ulonglong2*)(vB + (buf * TILE_P + lp) * CSTRIDE);

        #pragma unroll
        for (int c = 0; c < CIN; c++) {
            const int t = k * CIN + c;
            ulonglong2 va = v2[c * 2 + 0];   // (b0,b1),(b2,b3)
            ulonglong2 vb = v2[c * 2 + 1];   // (b4,b5),(b6,b7)
            float4 w = w4[t * 8 + og];
            unsigned long long wp0 = pack2(w.x), wp1 = pack2(w.y),
                               wp2 = pack2(w.z), wp3 = pack2(w.w);
            acc[0][0] = ffma2(va.x, wp0, acc[0][0]);
            acc[0][1] = ffma2(va.x, wp1, acc[0][1]);
            acc[0][2] = ffma2(va.x, wp2, acc[0][2]);
            acc[0][3] = ffma2(va.x, wp3, acc[0][3]);
            acc[1][0] = ffma2(va.y, wp0, acc[1][0]);
            acc[1][1] = ffma2(va.y, wp1, acc[1][1]);
            acc[1][2] = ffma2(va.y, wp2, acc[1][2]);
            acc[1][3] = ffma2(va.y, wp3, acc[1][3]);
            acc[2][0] = ffma2(vb.x, wp0, acc[2][0]);
            acc[2][1] = ffma2(vb.x, wp1, acc[2][1]);
            acc[2][2] = ffma2(vb.x, wp2, acc[2][2]);
            acc[2][3] = ffma2(vb.x, wp3, acc[2][3]);
            acc[3][0] = ffma2(vb.y, wp0, acc[3][0]);
            acc[3][1] = ffma2(vb.y, wp1, acc[3][1]);
            acc[3][2] = ffma2(vb.y, wp2, acc[3][2]);
            acc[3][3] = ffma2(vb.y, wp3, acc[3][3]);
        }
        // all threads must finish reading buf before the load for k+2
        // (issued at top of iteration k+1) overwrites it
        __syncthreads();
    }

    // epilogue: bias + stage to smem for coalesced global writes
    float4 bs = ((const float4*)bias)[og];
    float bi[4] = {bs.x, bs.y, bs.z, bs.w};
    #pragma unroll
    for (int j = 0; j < 4; j++) {
        #pragma unroll
        for (int i = 0; i < 4; i++) {
            float lo = __uint_as_float((unsigned)(acc[j][i] & 0xffffffffu));
            float hi = __uint_as_float((unsigned)(acc[j][i] >> 32));
            int o = og * 4 + i;
            oS[((2 * j)     * COUT + o) * (TILE_P + 1) + lp] = lo + bi[i];
            oS[((2 * j + 1) * COUT + o) * (TILE_P + 1) + lp] = hi + bi[i];
        }
    }
    __syncthreads();

    #pragma unroll
    for (int i = tid; i < B * COUT * TILE_P; i += 256) {   // 8192
        int row = i >> 5, col = i & 31;     // row = b*32+o
        out[row * NPIX + p0 + col] = oS[row * (TILE_P + 1) + col];
    }
}

// ---------------------------------------------------------------------------
extern "C" void kernel_launch(void* const* d_in, const int* in_sizes, int n_in,
                              void* d_out, int out_size) {
    const float* x      = (const float*)d_in[0];
    const float* weight = (const float*)d_in[1];
    const float* bias   = (const float*)d_in[2];
    const int*   neigh  = (const int*)d_in[3];
    float*       out    = (float*)d_out;

    cudaFuncSetAttribute(conv_kernel,
                         cudaFuncAttributeMaxDynamicSharedMemorySize,
                         SMEM_BYTES);

    transpose_kernel<<<NPIX / 32, 256>>>(x);
    conv_kernel<<<NPIX / TILE_P, 256, SMEM_BYTES>>>(weight, bias, neigh, out);
}

// round 7
// speedup vs baseline: 1.0438x; 1.0438x over previous
#include <cuda_runtime.h>
#include <cuda_fp16.h>
#include <cstdint>

#define NSIDE 128
#define NPIX (12*NSIDE*NSIDE)   /* 196608 */
#define B 8
#define CIN 16
#define COUT 32
#define BC (B*CIN)              /* 128 */
#define TILE_P 32
#define CSTRIDE 132             /* f32 buffer row: 128 floats + 4 pad */
#define HROW 272                /* fp16 buffer row bytes: 256 + 16 pad (16B mult) */
#define WS_FLOATS 4608
#define VH_BYTES (2*TILE_P*HROW)              /* 17408 */
#define VF_FLOATS (TILE_P*CSTRIDE)            /* 4224 */
#define NS_INTS (TILE_P*9)                    /* 288 */
#define SMEM_BYTES (WS_FLOATS*4 + VH_BYTES + VF_FLOATS*4 + NS_INTS*4)  /* 53888 */

// scratch: transposed, fp16, zero-padded x  (pixel-major: xh[idx][c*8+b])
__device__ __half g_xh[(size_t)(NPIX + 1) * BC];

// ---------------------------------------------------------------------------
// Kernel A: transpose+convert x [B][CIN][NPIX] f32 -> xh [NPIX+1][c*8+b] fp16
// ---------------------------------------------------------------------------
__global__ void transpose_kernel(const float* __restrict__ x) {
    __shared__ float tile[BC * 33];
    const int tid  = threadIdx.x;
    const int idx0 = blockIdx.x * 32;

    #pragma unroll
    for (int i = tid; i < BC * 32; i += 256) {
        int r  = i >> 5;            // r = b*16 + c
        int j  = i & 31;
        int cc = (r & 15) * 8 + (r >> 4);
        tile[cc * 33 + j] = x[r * NPIX + idx0 + j];
    }
    __syncthreads();
    // write 64 half2 per pixel row (256B contiguous)
    __half2* xh2 = (__half2*)g_xh;
    #pragma unroll
    for (int i = tid; i < 32 * 64; i += 256) {
        int j  = i >> 6;            // pixel within tile
        int cp = i & 63;            // half2 index
        __half2 h = __floats2half2_rn(tile[(2 * cp) * 33 + j],
                                      tile[(2 * cp + 1) * 33 + j]);
        xh2[(size_t)(idx0 + j) * 64 + cp] = h;
    }
    if (blockIdx.x == 0 && tid < 64)
        xh2[(size_t)NPIX * 64 + tid] = __floats2half2_rn(0.0f, 0.0f);
}

// ---------------------------------------------------------------------------
// PTX helpers
// ---------------------------------------------------------------------------
__device__ __forceinline__ unsigned long long ffma2(unsigned long long a,
                                                    unsigned long long b,
                                                    unsigned long long c) {
    unsigned long long d;
    asm("fma.rn.f32x2 %0, %1, %2, %3;" : "=l"(d) : "l"(a), "l"(b), "l"(c));
    return d;
}
__device__ __forceinline__ unsigned long long pack2(float x) {
    unsigned long long r;
    unsigned u = __float_as_uint(x);
    asm("mov.b64 %0, {%1, %1};" : "=l"(r) : "r"(u));
    return r;
}
__device__ __forceinline__ void cp_async16(uint32_t dst_smem, const void* src) {
    asm volatile("cp.async.cg.shared.global [%0], [%1], 16;\n"
                 :: "r"(dst_smem), "l"(src));
}

// ---------------------------------------------------------------------------
// Kernel B: 32-pixel tiles, fp16-gathered double buffer + per-chunk f32
//           conversion; 2 CTAs/SM; thread tile = 8b x 4o
// ---------------------------------------------------------------------------
__global__ void __launch_bounds__(256, 2) conv_kernel(
    const float* __restrict__ weight,   // [COUT][CIN][9]
    const float* __restrict__ bias,     // [COUT]
    const int*   __restrict__ neigh,    // [NPIX][9]
    float*       __restrict__ out)      // [B][COUT][NPIX]
{
    extern __shared__ char smem[];
    float* wS = (float*)smem;                      // [9][16][32] = 4608 f
    char*  vH = smem + WS_FLOATS * 4;              // [2][32][HROW] fp16 chunks
    float* vF = (float*)(vH + VH_BYTES);           // [32][CSTRIDE] f32 chunk
    int*   nS = (int*)(vF + VF_FLOATS);            // [288]
    float* oS = (float*)smem;                      // epilogue overlay (33792B)

    const int tid = threadIdx.x;
    const int p0  = blockIdx.x * TILE_P;

    // stage weights as wS[k][c][o]
    for (int i = tid; i < WS_FLOATS; i += 256) {
        int k = i >> 9, rem = i & 511, c = rem >> 5, o = rem & 31;
        wS[i] = weight[o * 144 + c * 9 + k];
    }
    for (int i = tid; i < NS_INTS; i += 256) nS[i] = neigh[p0 * 9 + i];
    __syncthreads();

    const uint32_t vH_u32 = (uint32_t)__cvta_generic_to_shared(vH);

    // chunk loader: 32 rows x 256B fp16 -> 512 cp.async16 (2/thread)
    auto load_chunk = [&](int k, int buf) {
        #pragma unroll
        for (int j = 0; j < 2; j++) {
            int i   = tid + j * 256;           // 0..511
            int lp  = i >> 4, seg = i & 15;
            int idx = nS[lp * 9 + k];
            uint32_t dst = vH_u32 + (buf * TILE_P + lp) * HROW + seg * 16;
            cp_async16(dst, (const char*)g_xh + (size_t)idx * 256 + seg * 16);
        }
        asm volatile("cp.async.commit_group;\n" ::: "memory");
    };

    load_chunk(0, 0);

    // compute mapping: thread (lp, og) -> pixel p0+lp, outputs og*4..og*4+3
    const int lp = tid >> 3;
    const int og = tid & 7;

    unsigned long long acc[4][4];
    #pragma unroll
    for (int j = 0; j < 4; j++)
        #pragma unroll
        for (int i = 0; i < 4; i++) acc[j][i] = 0ULL;

    const float4* w4 = (const float4*)wS;

    for (int k = 0; k < 9; k++) {
        if (k + 1 < 9) load_chunk(k + 1, (k + 1) & 1);
        if (k + 1 < 9) asm volatile("cp.async.wait_group 1;\n" ::: "memory");
        else           asm volatile("cp.async.wait_group 0;\n" ::: "memory");
        __syncthreads();   // chunk k (fp16) ready; compute k-1 done -> vF free

        // convert fp16 chunk -> vF (f32), 2 x (8 halves -> 8 floats) per thread
        {
            const int buf = k & 1;
            #pragma unroll
            for (int j = 0; j < 2; j++) {
                int u    = tid + j * 256;          // 0..511
                int ulp  = u >> 4, hseg = u & 15;
                uint4 h4 = *(const uint4*)(vH + (buf * TILE_P + ulp) * HROW + hseg * 16);
                float2 f0 = __half22float2(*(const __half2*)&h4.x);
                float2 f1 = __half22float2(*(const __half2*)&h4.y);
                float2 f2 = __half22float2(*(const __half2*)&h4.z);
                float2 f3 = __half22float2(*(const __half2*)&h4.w);
                float* d = vF + ulp * CSTRIDE + hseg * 8;
                *(float4*)(d)     = make_float4(f0.x, f0.y, f1.x, f1.y);
                *(float4*)(d + 4) = make_float4(f2.x, f2.y, f3.x, f3.y);
            }
        }
        __syncthreads();   // vF fully converted

        const ulonglong2* v2 = (const ulonglong2*)(vF + lp * CSTRIDE);

        #pragma unroll
        for (int c = 0; c < CIN; c++) {
            const int t = k * CIN + c;
            ulonglong2 va = v2[c * 2 + 0];   // (b0,b1),(b2,b3)
            ulonglong2 vb = v2[c * 2 + 1];   // (b4,b5),(b6,b7)
            float4 w = w4[t * 8 + og];
            unsigned long long wp0 = pack2(w.x), wp1 = pack2(w.y),
                               wp2 = pack2(w.z), wp3 = pack2(w.w);
            acc[0][0] = ffma2(va.x, wp0, acc[0][0]);
            acc[0][1] = ffma2(va.x, wp1, acc[0][1]);
            acc[0][2] = ffma2(va.x, wp2, acc[0][2]);
            acc[0][3] = ffma2(va.x, wp3, acc[0][3]);
            acc[1][0] = ffma2(va.y, wp0, acc[1][0]);
            acc[1][1] = ffma2(va.y, wp1, acc[1][1]);
            acc[1][2] = ffma2(va.y, wp2, acc[1][2]);
            acc[1][3] = ffma2(va.y, wp3, acc[1][3]);
            acc[2][0] = ffma2(vb.x, wp0, acc[2][0]);
            acc[2][1] = ffma2(vb.x, wp1, acc[2][1]);
            acc[2][2] = ffma2(vb.x, wp2, acc[2][2]);
            acc[2][3] = ffma2(vb.x, wp3, acc[2][3]);
            acc[3][0] = ffma2(vb.y, wp0, acc[3][0]);
            acc[3][1] = ffma2(vb.y, wp1, acc[3][1]);
            acc[3][2] = ffma2(vb.y, wp2, acc[3][2]);
            acc[3][3] = ffma2(vb.y, wp3, acc[3][3]);
        }
        // no trailing sync: top-of-loop sync orders compute(k) before convert(k+1)
    }
    __syncthreads();   // all compute done before oS overlays wS/vH

    // epilogue: bias + stage to smem for coalesced global writes
    float4 bs = ((const float4*)bias)[og];
    float bi[4] = {bs.x, bs.y, bs.z, bs.w};
    #pragma unroll
    for (int j = 0; j < 4; j++) {
        #pragma unroll
        for (int i = 0; i < 4; i++) {
            float lo = __uint_as_float((unsigned)(acc[j][i] & 0xffffffffu));
            float hi = __uint_as_float((unsigned)(acc[j][i] >> 32));
            int o = og * 4 + i;
            oS[((2 * j)     * COUT + o) * (TILE_P + 1) + lp] = lo + bi[i];
            oS[((2 * j + 1) * COUT + o) * (TILE_P + 1) + lp] = hi + bi[i];
        }
    }
    __syncthreads();

    #pragma unroll
    for (int i = tid; i < B * COUT * TILE_P; i += 256) {   // 8192
        int row = i >> 5, col = i & 31;     // row = b*32+o
        out[row * NPIX + p0 + col] = oS[row * (TILE_P + 1) + col];
    }
}

// ---------------------------------------------------------------------------
extern "C" void kernel_launch(void* const* d_in, const int* in_sizes, int n_in,
                              void* d_out, int out_size) {
    const float* x      = (const float*)d_in[0];
    const float* weight = (const float*)d_in[1];
    const float* bias   = (const float*)d_in[2];
    const int*   neigh  = (const int*)d_in[3];
    float*       out    = (float*)d_out;

    cudaFuncSetAttribute(conv_kernel,
                         cudaFuncAttributeMaxDynamicSharedMemorySize,
                         SMEM_BYTES);

    transpose_kernel<<<NPIX / 32, 256>>>(x);
    conv_kernel<<<NPIX / TILE_P, 256, SMEM_BYTES>>>(weight, bias, neigh, out);
}

// round 8
// speedup vs baseline: 1.1898x; 1.1399x over previous
#include <cuda_runtime.h>
#include <cstdint>

#define NSIDE 128
#define NPIX (12*NSIDE*NSIDE)   /* 196608 */
#define B 8
#define CIN 16
#define COUT 32
#define BC (B*CIN)              /* 128 */
#define TILE_P 32               /* 8 warps x 4 pixels */
#define CSTRIDE 132             /* row: 128 floats + 4 pad */
#define WS_FLOATS 4608
#define VB_FLOATS (8*2*4*CSTRIDE)   /* 8448: per-warp double buffers */
#define NS_INTS (TILE_P*9)          /* 288 */
#define SMEM_BYTES ((WS_FLOATS + VB_FLOATS)*4 + NS_INTS*4)   /* 53376 */

// scratch: transposed, zero-padded x  (pixel-major: xt[idx][c*8+b])
__device__ float g_xt[(NPIX + 1) * BC];

// ---------------------------------------------------------------------------
// Kernel A: transpose x [B][CIN][NPIX] -> xt [NPIX+1][c*8+b], row NPIX = zeros
// ---------------------------------------------------------------------------
__global__ void transpose_kernel(const float* __restrict__ x) {
    __shared__ float tile[BC * 33];
    const int tid  = threadIdx.x;
    const int idx0 = blockIdx.x * 32;

    #pragma unroll
    for (int i = tid; i < BC * 32; i += 256) {
        int r  = i >> 5;            // r = b*16 + c
        int j  = i & 31;
        int cc = (r & 15) * 8 + (r >> 4);
        tile[cc * 33 + j] = x[r * NPIX + idx0 + j];
    }
    __syncthreads();
    #pragma unroll
    for (int i = tid; i < BC * 32; i += 256) {
        int j  = i >> 7;
        int cc = i & 127;
        g_xt[(idx0 + j) * BC + cc] = tile[cc * 33 + j];
    }
    if (blockIdx.x == 0 && tid < BC) g_xt[NPIX * BC + tid] = 0.0f;
}

// ---------------------------------------------------------------------------
// PTX helpers
// ---------------------------------------------------------------------------
__device__ __forceinline__ unsigned long long ffma2(unsigned long long a,
                                                    unsigned long long b,
                                                    unsigned long long c) {
    unsigned long long d;
    asm("fma.rn.f32x2 %0, %1, %2, %3;" : "=l"(d) : "l"(a), "l"(b), "l"(c));
    return d;
}
__device__ __forceinline__ unsigned long long pack2(float x) {
    unsigned long long r;
    unsigned u = __float_as_uint(x);
    asm("mov.b64 %0, {%1, %1};" : "=l"(r) : "r"(u));
    return r;
}
__device__ __forceinline__ void cp_async16(uint32_t dst_smem, const void* src) {
    asm volatile("cp.async.cg.shared.global [%0], [%1], 16;\n"
                 :: "r"(dst_smem), "l"(src));
}

// ---------------------------------------------------------------------------
// Kernel B: warp-autonomous — each warp owns 4 pixels, its own double-buffered
//           cp.async gather, NO __syncthreads in the main loop.
//           thread tile = 8b x 4o  (lane = lp2*8 + og)
// ---------------------------------------------------------------------------
__global__ void __launch_bounds__(256, 2) conv_kernel(
    const float* __restrict__ weight,   // [COUT][CIN][9]
    const float* __restrict__ bias,     // [COUT]
    const int*   __restrict__ neigh,    // [NPIX][9]
    float*       __restrict__ out)      // [B][COUT][NPIX]
{
    extern __shared__ char smem[];
    float* wS = (float*)smem;                      // [9][16][32] = 4608 f
    float* vB = wS + WS_FLOATS;                    // [8 warps][2][4][CSTRIDE]
    int*   nS = (int*)(vB + VB_FLOATS);            // [288]
    float* oS = (float*)smem;                      // epilogue overlay (33792B)

    const int tid  = threadIdx.x;
    const int wid  = tid >> 5;
    const int lane = tid & 31;
    const int p0   = blockIdx.x * TILE_P;

    // stage weights as wS[k][c][o]
    for (int i = tid; i < WS_FLOATS; i += 256) {
        int k = i >> 9, rem = i & 511, c = rem >> 5, o = rem & 31;
        wS[i] = weight[o * 144 + c * 9 + k];
    }
    for (int i = tid; i < NS_INTS; i += 256) nS[i] = neigh[p0 * 9 + i];
    __syncthreads();   // the only pre-loop barrier

    const uint32_t vB_u32 = (uint32_t)__cvta_generic_to_shared(vB);
    float* vW = vB + wid * (2 * 4 * CSTRIDE);            // this warp's buffers
    const uint32_t vW_u32 = vB_u32 + wid * (2 * 4 * CSTRIDE) * 4;

    // per-warp chunk loader: 4 rows x 512B = 4 warp-wide cp.async16
    auto load_chunk = [&](int k, int buf) {
        #pragma unroll
        for (int j = 0; j < 4; j++) {
            int idx = nS[(wid * 4 + j) * 9 + k];
            uint32_t dst = vW_u32 + ((buf * 4 + j) * CSTRIDE + lane * 4) * 4;
            cp_async16(dst, g_xt + (size_t)idx * BC + lane * 4);
        }
        asm volatile("cp.async.commit_group;\n" ::: "memory");
    };

    load_chunk(0, 0);

    // compute mapping: lane (lp2, og) -> pixel p0 + wid*4 + lp2, outs og*4..+3
    const int lp2 = lane >> 3;
    const int og  = lane & 7;

    unsigned long long acc[4][4];
    #pragma unroll
    for (int j = 0; j < 4; j++)
        #pragma unroll
        for (int i = 0; i < 4; i++) acc[j][i] = 0ULL;

    const float4* w4 = (const float4*)wS;

    for (int k = 0; k < 9; k++) {
        if (k + 1 < 9) {
            load_chunk(k + 1, (k + 1) & 1);
            asm volatile("cp.async.wait_group 1;\n" ::: "memory");
        } else {
            asm volatile("cp.async.wait_group 0;\n" ::: "memory");
        }
        __syncwarp();   // lane x reads bytes copied by other lanes of this warp

        const ulonglong2* v2 =
            (const ulonglong2*)(vW + ((k & 1) * 4 + lp2) * CSTRIDE);

        #pragma unroll
        for (int c = 0; c < CIN; c++) {
            const int t = k * CIN + c;
            ulonglong2 va = v2[c * 2 + 0];   // (b0,b1),(b2,b3)
            ulonglong2 vb = v2[c * 2 + 1];   // (b4,b5),(b6,b7)
            float4 w = w4[t * 8 + og];
            unsigned long long wp0 = pack2(w.x), wp1 = pack2(w.y),
                               wp2 = pack2(w.z), wp3 = pack2(w.w);
            acc[0][0] = ffma2(va.x, wp0, acc[0][0]);
            acc[0][1] = ffma2(va.x, wp1, acc[0][1]);
            acc[0][2] = ffma2(va.x, wp2, acc[0][2]);
            acc[0][3] = ffma2(va.x, wp3, acc[0][3]);
            acc[1][0] = ffma2(va.y, wp0, acc[1][0]);
            acc[1][1] = ffma2(va.y, wp1, acc[1][1]);
            acc[1][2] = ffma2(va.y, wp2, acc[1][2]);
            acc[1][3] = ffma2(va.y, wp3, acc[1][3]);
            acc[2][0] = ffma2(vb.x, wp0, acc[2][0]);
            acc[2][1] = ffma2(vb.x, wp1, acc[2][1]);
            acc[2][2] = ffma2(vb.x, wp2, acc[2][2]);
            acc[2][3] = ffma2(vb.x, wp3, acc[2][3]);
            acc[3][0] = ffma2(vb.y, wp0, acc[3][0]);
            acc[3][1] = ffma2(vb.y, wp1, acc[3][1]);
            acc[3][2] = ffma2(vb.y, wp2, acc[3][2]);
            acc[3][3] = ffma2(vb.y, wp3, acc[3][3]);
        }
        __syncwarp();   // all lanes done reading buf before it is re-filled
    }

    __syncthreads();   // all warps done computing before oS overlays wS/vB

    // epilogue: bias + stage to smem for coalesced global writes
    const int lp = wid * 4 + lp2;
    float4 bs = ((const float4*)bias)[og];
    float bi[4] = {bs.x, bs.y, bs.z, bs.w};
    #pragma unroll
    for (int j = 0; j < 4; j++) {
        #pragma unroll
        for (int i = 0; i < 4; i++) {
            float lo = __uint_as_float((unsigned)(acc[j][i] & 0xffffffffu));
            float hi = __uint_as_float((unsigned)(acc[j][i] >> 32));
            int o = og * 4 + i;
            oS[((2 * j)     * COUT + o) * (TILE_P + 1) + lp] = lo + bi[i];
            oS[((2 * j + 1) * COUT + o) * (TILE_P + 1) + lp] = hi + bi[i];
        }
    }
    __syncthreads();

    #pragma unroll
    for (int i = tid; i < B * COUT * TILE_P; i += 256) {   // 8192
        int row = i >> 5, col = i & 31;     // row = b*32+o
        out[row * NPIX + p0 + col] = oS[row * (TILE_P + 1) + col];
    }
}

// ---------------------------------------------------------------------------
extern "C" void kernel_launch(void* const* d_in, const int* in_sizes, int n_in,
                              void* d_out, int out_size) {
    const float* x      = (const float*)d_in[0];
    const float* weight = (const float*)d_in[1];
    const float* bias   = (const float*)d_in[2];
    const int*   neigh  = (const int*)d_in[3];
    float*       out    = (float*)d_out;

    cudaFuncSetAttribute(conv_kernel,
                         cudaFuncAttributeMaxDynamicSharedMemorySize,
                         SMEM_BYTES);

    transpose_kernel<<<NPIX / 32, 256>>>(x);
    conv_kernel<<<NPIX / TILE_P, 256, SMEM_BYTES>>>(weight, bias, neigh, out);
}

// round 10
// speedup vs baseline: 1.8157x; 1.5260x over previous
#include <cuda_runtime.h>
#include <cuda_fp16.h>
#include <cstdint>

#define NSIDE 128
#define NPIX (12*NSIDE*NSIDE)   /* 196608 */
#define B 8
#define CIN 16
#define COUT 32
#define TILE_P 16
#define NT (NPIX/TILE_P)        /* 12288 */

#define ASTRIDE 304             /* bytes per A row (144 halves = 288B + 16 pad) */
#define A_OFF 0
#define A_BYTES (128*ASTRIDE)   /* 38912 */
#define B_OFF A_BYTES
#define B_BYTES (32*ASTRIDE)    /* 9728 */
#define NS_OFF (B_OFF + B_BYTES)        /* 48640 */
#define BS_OFF (NS_OFF + 144*4)         /* 49216 */
#define SMEM_BYTES (BS_OFF + 128)       /* 49344 */
#define OSTRIDE 17              /* oS row stride in floats */

// transposed fp16 x, pixel-major rows of [b*16+c], row NPIX = zeros
__device__ __align__(256) __half g_xh[(size_t)(NPIX + 1) * 128];

// ---------------------------------------------------------------------------
// Kernel A: transpose+convert x [B][CIN][NPIX] f32 -> g_xh [NPIX+1][b*16+c]
// ---------------------------------------------------------------------------
__global__ void transpose_kernel(const float* __restrict__ x) {
    __shared__ float tile[128 * 33];
    const int tid  = threadIdx.x;
    const int idx0 = blockIdx.x * 32;

    #pragma unroll
    for (int i = tid; i < 128 * 32; i += 256) {
        int r = i >> 5;             // r = b*16 + c (x row order)
        int j = i & 31;
        tile[r * 33 + j] = x[r * NPIX + idx0 + j];
    }
    __syncthreads();
    __half2* xh2 = (__half2*)g_xh;
    #pragma unroll
    for (int i = tid; i < 32 * 64; i += 256) {
        int j  = i >> 6;            // pixel within tile
        int cp = i & 63;            // half2 index (adjacent c, same b)
        __half2 h = __floats2half2_rn(tile[(2 * cp) * 33 + j],
                                      tile[(2 * cp + 1) * 33 + j]);
        xh2[(size_t)(idx0 + j) * 64 + cp] = h;
    }
    if (blockIdx.x == 0 && tid < 64)
        xh2[(size_t)NPIX * 64 + tid] = __floats2half2_rn(0.0f, 0.0f);
}

// ---------------------------------------------------------------------------
// PTX helpers (all arch-agnostic: cp.async sm_80+, ldmatrix/mma sm_80+)
// ---------------------------------------------------------------------------
__device__ __forceinline__ void cp_async16(uint32_t dst_smem, const void* src) {
    asm volatile("cp.async.cg.shared.global [%0], [%1], 16;\n"
                 :: "r"(dst_smem), "l"(src));
}
__device__ __forceinline__ void ldsm_x4(uint32_t& r0, uint32_t& r1,
                                        uint32_t& r2, uint32_t& r3,
                                        uint32_t addr) {
    asm volatile("ldmatrix.sync.aligned.m8n8.x4.shared.b16 {%0,%1,%2,%3}, [%4];"
                 : "=r"(r0), "=r"(r1), "=r"(r2), "=r"(r3) : "r"(addr));
}
__device__ __forceinline__ void mma_16816(float& c0, float& c1, float& c2, float& c3,
                                          uint32_t a0, uint32_t a1, uint32_t a2, uint32_t a3,
                                          uint32_t b0, uint32_t b1) {
    asm volatile(
        "mma.sync.aligned.m16n8k16.row.col.f32.f16.f16.f32 "
        "{%0,%1,%2,%3}, {%4,%5,%6,%7}, {%8,%9}, {%0,%1,%2,%3};"
        : "+f"(c0), "+f"(c1), "+f"(c2), "+f"(c3)
        : "r"(a0), "r"(a1), "r"(a2), "r"(a3), "r"(b0), "r"(b1));
}

// ---------------------------------------------------------------------------
// Kernel B: per-CTA 16-pixel tile GEMM via mma.sync (M=128,N=32,K=144)
//   warp w owns A rows m = w*16 .. w*16+15  (m = p*8 + b, p = tile pixel)
// ---------------------------------------------------------------------------
__global__ void __launch_bounds__(256, 3) conv_kernel(
    const float* __restrict__ weight,   // [COUT][CIN][9]
    const float* __restrict__ bias,     // [COUT]
    const int*   __restrict__ neigh,    // [NPIX][9]
    float*       __restrict__ out)      // [B][COUT][NPIX]
{
    extern __shared__ char smem[];
    const int tid  = threadIdx.x;
    const int wid  = tid >> 5;
    const int lane = tid & 31;
    const int p0   = blockIdx.x * TILE_P;

    uint32_t smem_u32;
    asm("{ .reg .u64 t; cvta.to.shared.u64 t, %1; cvt.u32.u64 %0, t; }"
        : "=r"(smem_u32) : "l"(smem));
    int*   nS = (int*)(smem + NS_OFF);
    float* bS = (float*)(smem + BS_OFF);
    float* oS = (float*)smem;           // epilogue overlay on A region

    // ---- prologue: weights -> B smem [o][k], k = kk*16 + c  ----
    for (int i = tid; i < COUT * CIN * 9; i += 256) {
        int o = i / 144, rem = i - o * 144, c = rem / 9, kk = rem - c * 9;
        *(__half*)(smem + B_OFF + o * ASTRIDE + (kk * 16 + c) * 2) =
            __float2half_rn(weight[i]);
    }
    if (tid < 144) nS[tid] = neigh[blockIdx.x * 144 + tid];
    if (tid < 32)  bS[tid] = bias[tid];

    // ---- gather A: 2304 cp.async16, (p,kk,b,h) ----
    #pragma unroll
    for (int j = 0; j < 9; j++) {
        int i   = tid + j * 256;        // 0..2303
        int h   = i & 1;
        int b   = (i >> 1) & 7;
        int row = i >> 4;               // p*9 + kk
        int p   = row / 9, kk = row - p * 9;
        // nS written by this thread's own block? ensure visibility: rows 0..143
        // are written by threads 0..143; thread tid reads row (tid+j*256)>>4.
        // j=0: row=tid>>4 <= 15 written by low threads — need sync first.
        (void)p; (void)kk; (void)b; (void)h;
        break;
    }
    __syncthreads();   // nS, B, bS staged

    #pragma unroll
    for (int j = 0; j < 9; j++) {
        int i   = tid + j * 256;
        int h   = i & 1;
        int b   = (i >> 1) & 7;
        int row = i >> 4;               // p*9 + kk
        int p   = row / 9, kk = row - p * 9;
        int idx = nS[row];
        uint32_t dst = smem_u32 + A_OFF + (uint32_t)(p * 8 + b) * ASTRIDE
                     + kk * 32 + h * 16;
        cp_async16(dst, (const char*)g_xh + (size_t)idx * 256 + b * 32 + h * 16);
    }
    asm volatile("cp.async.commit_group;\n" ::: "memory");
    asm volatile("cp.async.wait_group 0;\n" ::: "memory");
    __syncthreads();   // A tile complete

    // ---- GEMM: 9 k-steps, 4 n-tiles ----
    float acc[4][4];
    #pragma unroll
    for (int j = 0; j < 4; j++)
        #pragma unroll
        for (int i = 0; i < 4; i++) acc[j][i] = 0.0f;

    // A ldmatrix lane address: rows m = w*16 + (lane&15), k halves offset (lane>>4)*8
    uint32_t aAddr = smem_u32 + A_OFF
                   + (uint32_t)(wid * 16 + (lane & 15)) * ASTRIDE
                   + (lane >> 4) * 16;
    // B ldmatrix lane address: o = (lane>>4)*8 + (lane&7), k offset ((lane>>3)&1)*16B
    uint32_t bAddr = smem_u32 + B_OFF
                   + (uint32_t)((lane >> 4) * 8 + (lane & 7)) * ASTRIDE
                   + ((lane >> 3) & 1) * 16;

    #pragma unroll
    for (int kk = 0; kk < 9; kk++) {
        uint32_t a0, a1, a2, a3, b0, b1, b2, b3, b4, b5, b6, b7;
        ldsm_x4(a0, a1, a2, a3, aAddr + kk * 32);
        ldsm_x4(b0, b1, b2, b3, bAddr + kk * 32);                 // o 0..15
        ldsm_x4(b4, b5, b6, b7, bAddr + 16 * ASTRIDE + kk * 32);  // o 16..31
        mma_16816(acc[0][0], acc[0][1], acc[0][2], acc[0][3], a0, a1, a2, a3, b0, b1);
        mma_16816(acc[1][0], acc[1][1], acc[1][2], acc[1][3], a0, a1, a2, a3, b2, b3);
        mma_16816(acc[2][0], acc[2][1], acc[2][2], acc[2][3], a0, a1, a2, a3, b4, b5);
        mma_16816(acc[3][0], acc[3][1], acc[3][2], acc[3][3], a0, a1, a2, a3, b6, b7);
    }
    __syncthreads();   // all A reads done before oS overlay

    // ---- epilogue: frags -> oS[(o*8+b)*17 + p] with bias ----
    // thread: g = lane>>2 (= b), tg = lane&3; c0,c1 -> p=w*2; c2,c3 -> p=w*2+1
    {
        const int g  = lane >> 2;
        const int tg = lane & 3;
        #pragma unroll
        for (int j = 0; j < 4; j++) {
            int o0 = j * 8 + tg * 2;
            float bi0 = bS[o0], bi1 = bS[o0 + 1];
            oS[(o0       * 8 + g) * OSTRIDE + wid * 2    ] = acc[j][0] + bi0;
            oS[((o0 + 1) * 8 + g) * OSTRIDE + wid * 2    ] = acc[j][1] + bi1;
            oS[(o0       * 8 + g) * OSTRIDE + wid * 2 + 1] = acc[j][2] + bi0;
            oS[((o0 + 1) * 8 + g) * OSTRIDE + wid * 2 + 1] = acc[j][3] + bi1;
        }
    }
    __syncthreads();

    // ---- coalesced out: row (b*32+o) gets 16 contiguous pixels (64B) ----
    #pragma unroll
    for (int j = 0; j < 16; j++) {
        int i   = tid + j * 256;        // i = row*16 + p, row = b*32 + o
        int row = i >> 4, p = i & 15;
        int b   = row >> 5, o = row & 31;
        out[row * NPIX + p0 + p] = oS[(o * 8 + b) * OSTRIDE + p];
    }
}

// ---------------------------------------------------------------------------
extern "C" void kernel_launch(void* const* d_in, const int* in_sizes, int n_in,
                              void* d_out, int out_size) {
    const float* x      = (const float*)d_in[0];
    const float* weight = (const float*)d_in[1];
    const float* bias   = (const float*)d_in[2];
    const int*   neigh  = (const int*)d_in[3];
    float*       out    = (float*)d_out;

    cudaFuncSetAttribute(conv_kernel,
                         cudaFuncAttributeMaxDynamicSharedMemorySize,
                         SMEM_BYTES);

    transpose_kernel<<<NPIX / 32, 256>>>(x);
    conv_kernel<<<NT, 256, SMEM_BYTES>>>(weight, bias, neigh, out);
}

// round 12
// speedup vs baseline: 2.2199x; 1.2226x over previous
#include <cuda_runtime.h>
#include <cuda_fp16.h>
#include <cstdint>

#define NSIDE 128
#define NPIX (12*NSIDE*NSIDE)   /* 196608 */
#define B 8
#define CIN 16
#define COUT 32
#define TILE_P 16
#define NT (NPIX/TILE_P)        /* 12288 */
#define GRID 296                /* persistent: 2 CTAs x 148 SMs */

#define ASTRIDE 304             /* bytes per A/B row (144 halves = 288B + 16 pad) */
#define A_BYTES (128*ASTRIDE)   /* 38912 per buffer */
#define A0_OFF 0
#define A1_OFF A_BYTES
#define B_OFF (2*A_BYTES)                 /* 77824 */
#define B_BYTES (32*ASTRIDE)              /* 9728 */
#define OS_OFF (B_OFF + B_BYTES)          /* 87552 */
#define OS_BYTES (256*17*4)               /* 17408  (FIX R11: rows go to 255) */
#define NS_OFF (OS_OFF + OS_BYTES)        /* 104960 */
#define BS_OFF (NS_OFF + 144*4)           /* 105536 */
#define SMEM_BYTES (BS_OFF + 128)         /* 105664; x2 CTA = 211328 <= 228KB/SM */
#define OSTRIDE 17

// transposed fp16 x, pixel-major rows of [b*16+c], row NPIX = zeros
__device__ __align__(256) __half g_xh[(size_t)(NPIX + 1) * 128];

// ---------------------------------------------------------------------------
// Kernel A: transpose+convert x [B][CIN][NPIX] f32 -> g_xh [NPIX+1][b*16+c]
// ---------------------------------------------------------------------------
__global__ void transpose_kernel(const float* __restrict__ x) {
    __shared__ float tile[128 * 33];
    const int tid  = threadIdx.x;
    const int idx0 = blockIdx.x * 32;

    #pragma unroll
    for (int i = tid; i < 128 * 32; i += 256) {
        int r = i >> 5;             // r = b*16 + c
        int j = i & 31;
        tile[r * 33 + j] = x[r * NPIX + idx0 + j];
    }
    __syncthreads();
    __half2* xh2 = (__half2*)g_xh;
    #pragma unroll
    for (int i = tid; i < 32 * 64; i += 256) {
        int j  = i >> 6;
        int cp = i & 63;
        __half2 h = __floats2half2_rn(tile[(2 * cp) * 33 + j],
                                      tile[(2 * cp + 1) * 33 + j]);
        xh2[(size_t)(idx0 + j) * 64 + cp] = h;
    }
    if (blockIdx.x == 0 && tid < 64)
        xh2[(size_t)NPIX * 64 + tid] = __floats2half2_rn(0.0f, 0.0f);
}

// ---------------------------------------------------------------------------
// PTX helpers (arch-agnostic under compute_103)
// ---------------------------------------------------------------------------
__device__ __forceinline__ void cp_async16(uint32_t dst_smem, const void* src) {
    asm volatile("cp.async.cg.shared.global [%0], [%1], 16;\n"
                 :: "r"(dst_smem), "l"(src));
}
__device__ __forceinline__ void ldsm_x4(uint32_t& r0, uint32_t& r1,
                                        uint32_t& r2, uint32_t& r3,
                                        uint32_t addr) {
    asm volatile("ldmatrix.sync.aligned.m8n8.x4.shared.b16 {%0,%1,%2,%3}, [%4];"
                 : "=r"(r0), "=r"(r1), "=r"(r2), "=r"(r3) : "r"(addr));
}
__device__ __forceinline__ void mma_16816(float& c0, float& c1, float& c2, float& c3,
                                          uint32_t a0, uint32_t a1, uint32_t a2, uint32_t a3,
                                          uint32_t b0, uint32_t b1) {
    asm volatile(
        "mma.sync.aligned.m16n8k16.row.col.f32.f16.f16.f32 "
        "{%0,%1,%2,%3}, {%4,%5,%6,%7}, {%8,%9}, {%0,%1,%2,%3};"
        : "+f"(c0), "+f"(c1), "+f"(c2), "+f"(c3)
        : "r"(a0), "r"(a1), "r"(a2), "r"(a3), "r"(b0), "r"(b1));
}

// ---------------------------------------------------------------------------
// Kernel B: persistent, double-buffered gather + mma.sync GEMM per 16-px tile
// ---------------------------------------------------------------------------
__global__ void __launch_bounds__(256, 2) conv_kernel(
    const float* __restrict__ weight,   // [COUT][CIN][9]
    const float* __restrict__ bias,     // [COUT]
    const int*   __restrict__ neigh,    // [NPIX][9]
    float*       __restrict__ out)      // [B][COUT][NPIX]
{
    extern __shared__ char smem[];
    const int tid  = threadIdx.x;
    const int wid  = tid >> 5;
    const int lane = tid & 31;

    uint32_t smem_u32;
    asm("{ .reg .u64 t; cvta.to.shared.u64 t, %1; cvt.u32.u64 %0, t; }"
        : "=r"(smem_u32) : "l"(smem));
    int*   nS = (int*)(smem + NS_OFF);
    float* bS = (float*)(smem + BS_OFF);
    float* oS = (float*)(smem + OS_OFF);

    // ---- one-time prologue: weights [o][k] (k = kk*16+c), bias ----
    for (int i = tid; i < COUT * CIN * 9; i += 256) {
        int o = i / 144, rem = i - o * 144, c = rem / 9, kk = rem - c * 9;
        *(__half*)(smem + B_OFF + o * ASTRIDE + (kk * 16 + c) * 2) =
            __float2half_rn(weight[i]);
    }
    if (tid < 32) bS[tid] = bias[tid];

    // per-thread gather constants (loop-invariant): 9 cp.asyncs per tile
    uint32_t dOff[9]; int rowv[9], sOff[9];
    #pragma unroll
    for (int j = 0; j < 9; j++) {
        int i   = tid + j * 256;
        int h   = i & 1;
        int b   = (i >> 1) & 7;
        int row = i >> 4;                     // p*9 + kk
        int p   = row / 9, kk = row - p * 9;
        rowv[j] = row;
        sOff[j] = b * 32 + h * 16;
        dOff[j] = (uint32_t)((p * 8 + b) * ASTRIDE + kk * 32 + h * 16);
    }

    auto gather = [&](uint32_t abase) {
        #pragma unroll
        for (int j = 0; j < 9; j++) {
            int idx = nS[rowv[j]];
            cp_async16(abase + dOff[j],
                       (const char*)g_xh + (size_t)idx * 256 + sOff[j]);
        }
        asm volatile("cp.async.commit_group;\n" ::: "memory");
    };

    // ldmatrix lane addresses (A base added per-buffer later)
    const uint32_t aLane = (uint32_t)(wid * 16 + (lane & 15)) * ASTRIDE
                         + (lane >> 4) * 16;
    const uint32_t bAddr = smem_u32 + B_OFF
                         + (uint32_t)((lane >> 4) * 8 + (lane & 7)) * ASTRIDE
                         + ((lane >> 3) & 1) * 16;

    int t   = blockIdx.x;
    int cur = 0;

    if (tid < 144) nS[tid] = neigh[t * 144 + tid];
    __syncthreads();                 // weights, bias, nS(t) staged
    gather(smem_u32 + A0_OFF);       // G(t) in flight

    while (t < NT) {
        const int tn = t + GRID;

        __syncthreads();             // all gathers issued -> nS reusable
        if (tn < NT && tid < 144) nS[tid] = neigh[tn * 144 + tid];
        __syncthreads();             // nS(tn) visible

        if (tn < NT) {
            gather(smem_u32 + (cur ? A0_OFF : A1_OFF));   // G(tn)
            asm volatile("cp.async.wait_group 1;\n" ::: "memory");  // G(t) done
        } else {
            asm volatile("cp.async.wait_group 0;\n" ::: "memory");
        }
        __syncthreads();             // A(t) visible to all warps

        // ---- GEMM on buffer cur ----
        float acc[4][4];
        #pragma unroll
        for (int j = 0; j < 4; j++)
            #pragma unroll
            for (int i = 0; i < 4; i++) acc[j][i] = 0.0f;

        const uint32_t aAddr = smem_u32 + (cur ? A1_OFF : A0_OFF) + aLane;

        #pragma unroll
        for (int kk = 0; kk < 9; kk++) {
            uint32_t a0, a1, a2, a3, b0, b1, b2, b3, b4, b5, b6, b7;
            ldsm_x4(a0, a1, a2, a3, aAddr + kk * 32);
            ldsm_x4(b0, b1, b2, b3, bAddr + kk * 32);                 // o 0..15
            ldsm_x4(b4, b5, b6, b7, bAddr + 16 * ASTRIDE + kk * 32);  // o 16..31
            mma_16816(acc[0][0], acc[0][1], acc[0][2], acc[0][3], a0, a1, a2, a3, b0, b1);
            mma_16816(acc[1][0], acc[1][1], acc[1][2], acc[1][3], a0, a1, a2, a3, b2, b3);
            mma_16816(acc[2][0], acc[2][1], acc[2][2], acc[2][3], a0, a1, a2, a3, b4, b5);
            mma_16816(acc[3][0], acc[3][1], acc[3][2], acc[3][3], a0, a1, a2, a3, b6, b7);
        }

        // ---- epilogue: frags -> oS with bias ----
        {
            const int g  = lane >> 2;       // = b
            const int tg = lane & 3;
            #pragma unroll
            for (int j = 0; j < 4; j++) {
                int o0 = j * 8 + tg * 2;
                float bi0 = bS[o0], bi1 = bS[o0 + 1];
                oS[(o0       * 8 + g) * OSTRIDE + wid * 2    ] = acc[j][0] + bi0;
                oS[((o0 + 1) * 8 + g) * OSTRIDE + wid * 2    ] = acc[j][1] + bi1;
                oS[(o0       * 8 + g) * OSTRIDE + wid * 2 + 1] = acc[j][2] + bi0;
                oS[((o0 + 1) * 8 + g) * OSTRIDE + wid * 2 + 1] = acc[j][3] + bi1;
            }
        }
        __syncthreads();             // oS staged

        const int p0 = t * TILE_P;
        #pragma unroll
        for (int j = 0; j < 16; j++) {
            int i   = tid + j * 256;        // i = row*16 + p, row = b*32+o
            int row = i >> 4, p = i & 15;
            int b   = row >> 5, o = row & 31;
            out[row * NPIX + p0 + p] = oS[(o * 8 + b) * OSTRIDE + p];
        }

        t = tn;
        cur ^= 1;
    }
}

// ---------------------------------------------------------------------------
extern "C" void kernel_launch(void* const* d_in, const int* in_sizes, int n_in,
                              void* d_out, int out_size) {
    const float* x      = (const float*)d_in[0];
    const float* weight = (const float*)d_in[1];
    const float* bias   = (const float*)d_in[2];
    const int*   neigh  = (const int*)d_in[3];
    float*       out    = (float*)d_out;

    cudaFuncSetAttribute(conv_kernel,
                         cudaFuncAttributeMaxDynamicSharedMemorySize,
                         SMEM_BYTES);

    transpose_kernel<<<NPIX / 32, 256>>>(x);
    conv_kernel<<<GRID, 256, SMEM_BYTES>>>(weight, bias, neigh, out);
}

// round 13
// speedup vs baseline: 2.2697x; 1.0224x over previous
#include <cuda_runtime.h>
#include <cuda_fp16.h>
#include <cstdint>

#define NSIDE 128
#define NPIX (12*NSIDE*NSIDE)   /* 196608 */
#define B 8
#define CIN 16
#define COUT 32
#define TILE_P 16
#define NT (NPIX/TILE_P)        /* 12288 */
#define GRID 296                /* persistent: 2 CTAs x 148 SMs */

#define ASTRIDE 304             /* bytes per A/B row (144 halves = 288B + 16 pad) */
#define A_BYTES (128*ASTRIDE)   /* 38912 per buffer */
#define A0_OFF 0
#define A1_OFF A_BYTES
#define B_OFF (2*A_BYTES)                 /* 77824 */
#define B_BYTES (32*ASTRIDE)              /* 9728 */
#define OS_OFF (B_OFF + B_BYTES)          /* 87552 */
#define OS_BYTES (256*17*4)               /* 17408 */
#define BS_OFF (OS_OFF + OS_BYTES)        /* 104960 */
#define SMEM_BYTES (BS_OFF + 128)         /* 105088; x2 = 210176 <= 228KB/SM */
#define OSTRIDE 17

// transposed fp16 x, pixel-major rows of [b*16+c], row NPIX = zeros
__device__ __align__(256) __half g_xh[(size_t)(NPIX + 1) * 128];

// ---------------------------------------------------------------------------
// Kernel A: transpose+convert x [B][CIN][NPIX] f32 -> g_xh [NPIX+1][b*16+c]
// ---------------------------------------------------------------------------
__global__ void transpose_kernel(const float* __restrict__ x) {
    __shared__ float tile[128 * 33];
    const int tid  = threadIdx.x;
    const int idx0 = blockIdx.x * 32;

    #pragma unroll
    for (int i = tid; i < 128 * 8; i += 256) {      // float4 loads
        int r  = i >> 3;
        int j4 = (i & 7) * 4;
        float4 v = *(const float4*)(x + r * NPIX + idx0 + j4);
        tile[r * 33 + j4 + 0] = v.x;
        tile[r * 33 + j4 + 1] = v.y;
        tile[r * 33 + j4 + 2] = v.z;
        tile[r * 33 + j4 + 3] = v.w;
    }
    __syncthreads();
    __half2* xh2 = (__half2*)g_xh;
    #pragma unroll
    for (int i = tid; i < 32 * 64; i += 256) {
        int j  = i >> 6;
        int cp = i & 63;
        __half2 h = __floats2half2_rn(tile[(2 * cp) * 33 + j],
                                      tile[(2 * cp + 1) * 33 + j]);
        xh2[(size_t)(idx0 + j) * 64 + cp] = h;
    }
    if (blockIdx.x == 0 && tid < 64)
        xh2[(size_t)NPIX * 64 + tid] = __floats2half2_rn(0.0f, 0.0f);
}

// ---------------------------------------------------------------------------
// PTX helpers (arch-agnostic under compute_103)
// ---------------------------------------------------------------------------
__device__ __forceinline__ void cp_async16(uint32_t dst_smem, const void* src) {
    asm volatile("cp.async.cg.shared.global [%0], [%1], 16;\n"
                 :: "r"(dst_smem), "l"(src));
}
__device__ __forceinline__ void ldsm_x4(uint32_t& r0, uint32_t& r1,
                                        uint32_t& r2, uint32_t& r3,
                                        uint32_t addr) {
    asm volatile("ldmatrix.sync.aligned.m8n8.x4.shared.b16 {%0,%1,%2,%3}, [%4];"
                 : "=r"(r0), "=r"(r1), "=r"(r2), "=r"(r3) : "r"(addr));
}
__device__ __forceinline__ void mma_16816(float& c0, float& c1, float& c2, float& c3,
                                          uint32_t a0, uint32_t a1, uint32_t a2, uint32_t a3,
                                          uint32_t b0, uint32_t b1) {
    asm volatile(
        "mma.sync.aligned.m16n8k16.row.col.f32.f16.f16.f32 "
        "{%0,%1,%2,%3}, {%4,%5,%6,%7}, {%8,%9}, {%0,%1,%2,%3};"
        : "+f"(c0), "+f"(c1), "+f"(c2), "+f"(c3)
        : "r"(a0), "r"(a1), "r"(a2), "r"(a3), "r"(b0), "r"(b1));
}

// ---------------------------------------------------------------------------
// Kernel B: persistent, double-buffered gather + mma.sync GEMM.
//   Neighbour indices live in REGISTERS, prefetched one tile ahead.
//   2 barriers per tile (was 4).
// ---------------------------------------------------------------------------
__global__ void __launch_bounds__(256, 2) conv_kernel(
    const float* __restrict__ weight,   // [COUT][CIN][9]
    const float* __restrict__ bias,     // [COUT]
    const int*   __restrict__ neigh,    // [NPIX][9]
    float*       __restrict__ out)      // [B][COUT][NPIX]
{
    extern __shared__ char smem[];
    const int tid  = threadIdx.x;
    const int wid  = tid >> 5;
    const int lane = tid & 31;

    uint32_t smem_u32;
    asm("{ .reg .u64 t; cvta.to.shared.u64 t, %1; cvt.u32.u64 %0, t; }"
        : "=r"(smem_u32) : "l"(smem));
    float* bS = (float*)(smem + BS_OFF);
    float* oS = (float*)(smem + OS_OFF);

    // ---- one-time prologue: weights [o][k] (k = kk*16+c), bias ----
    for (int i = tid; i < COUT * CIN * 9; i += 256) {
        int o = i / 144, rem = i - o * 144, c = rem / 9, kk = rem - c * 9;
        *(__half*)(smem + B_OFF + o * ASTRIDE + (kk * 16 + c) * 2) =
            __float2half_rn(weight[i]);
    }
    if (tid < 32) bS[tid] = bias[tid];

    // ---- per-thread gather constants ----
    // i = tid + j*256:  h = tid&1, b = (tid>>1)&7 (constant over j),
    //                   row = (tid>>4) + j*16
    const int hh    = tid & 1;
    const int bb    = (tid >> 1) & 7;
    const int rbase = tid >> 4;
    const char* xsrc = (const char*)g_xh + bb * 32 + hh * 16;

    uint32_t dOff[9];
    #pragma unroll
    for (int j = 0; j < 9; j++) {
        int row = rbase + j * 16;             // p*9 + kk
        int p   = row / 9, kk = row - p * 9;
        dOff[j] = (uint32_t)((p * 8 + bb) * ASTRIDE + kk * 32 + hh * 16);
    }

    int nidx[9];
    auto prefetch = [&](int t_) {
        const int* np = neigh + (size_t)t_ * 144 + rbase;
        #pragma unroll
        for (int j = 0; j < 9; j++) nidx[j] = __ldg(np + j * 16);
    };
    auto gather = [&](uint32_t abase) {
        #pragma unroll
        for (int j = 0; j < 9; j++)
            cp_async16(abase + dOff[j], xsrc + (size_t)nidx[j] * 256);
        asm volatile("cp.async.commit_group;\n" ::: "memory");
    };

    // ldmatrix lane addresses
    const uint32_t aLane = (uint32_t)(wid * 16 + (lane & 15)) * ASTRIDE
                         + (lane >> 4) * 16;
    const uint32_t bAddr = smem_u32 + B_OFF
                         + (uint32_t)((lane >> 4) * 8 + (lane & 7)) * ASTRIDE
                         + ((lane >> 3) & 1) * 16;

    int t   = blockIdx.x;
    int cur = 0;

    prefetch(t);
    gather(smem_u32 + A0_OFF);           // G(t) in flight
    if (t + GRID < NT) prefetch(t + GRID);   // nidx <- indices for tile t+GRID

    while (t < NT) {
        const int tn = t + GRID;

        if (tn < NT) {
            gather(smem_u32 + (cur ? A0_OFF : A1_OFF));   // G(tn), uses nidx(tn)
            asm volatile("cp.async.wait_group 1;\n" ::: "memory");  // G(t) done
        } else {
            asm volatile("cp.async.wait_group 0;\n" ::: "memory");
        }
        __syncthreads();     // A(t) visible; prev-iter oS reads done; weights ready

        if (tn + GRID < NT) prefetch(tn + GRID);   // hides under GEMM

        // ---- GEMM on buffer cur ----
        float acc[4][4];
        #pragma unroll
        for (int j = 0; j < 4; j++)
            #pragma unroll
            for (int i = 0; i < 4; i++) acc[j][i] = 0.0f;

        const uint32_t aAddr = smem_u32 + (cur ? A1_OFF : A0_OFF) + aLane;

        #pragma unroll
        for (int kk = 0; kk < 9; kk++) {
            uint32_t a0, a1, a2, a3, b0, b1, b2, b3, b4, b5, b6, b7;
            ldsm_x4(a0, a1, a2, a3, aAddr + kk * 32);
            ldsm_x4(b0, b1, b2, b3, bAddr + kk * 32);                 // o 0..15
            ldsm_x4(b4, b5, b6, b7, bAddr + 16 * ASTRIDE + kk * 32);  // o 16..31
            mma_16816(acc[0][0], acc[0][1], acc[0][2], acc[0][3], a0, a1, a2, a3, b0, b1);
            mma_16816(acc[1][0], acc[1][1], acc[1][2], acc[1][3], a0, a1, a2, a3, b2, b3);
            mma_16816(acc[2][0], acc[2][1], acc[2][2], acc[2][3], a0, a1, a2, a3, b4, b5);
            mma_16816(acc[3][0], acc[3][1], acc[3][2], acc[3][3], a0, a1, a2, a3, b6, b7);
        }

        // ---- epilogue: frags -> oS with bias ----
        {
            const int g  = lane >> 2;       // = b
            const int tg = lane & 3;
            #pragma unroll
            for (int j = 0; j < 4; j++) {
                int o0 = j * 8 + tg * 2;
                float bi0 = bS[o0], bi1 = bS[o0 + 1];
                oS[(o0       * 8 + g) * OSTRIDE + wid * 2    ] = acc[j][0] + bi0;
                oS[((o0 + 1) * 8 + g) * OSTRIDE + wid * 2    ] = acc[j][1] + bi1;
                oS[(o0       * 8 + g) * OSTRIDE + wid * 2 + 1] = acc[j][2] + bi0;
                oS[((o0 + 1) * 8 + g) * OSTRIDE + wid * 2 + 1] = acc[j][3] + bi1;
            }
        }
        __syncthreads();     // oS staged

        const int p0 = t * TILE_P;
        #pragma unroll
        for (int j = 0; j < 16; j++) {
            int i   = tid + j * 256;        // i = row*16 + p, row = b*32+o
            int row = i >> 4, p = i & 15;
            int b   = row >> 5, o = row & 31;
            out[row * NPIX + p0 + p] = oS[(o * 8 + b) * OSTRIDE + p];
        }

        t = tn;
        cur ^= 1;
    }
}

// ---------------------------------------------------------------------------
extern "C" void kernel_launch(void* const* d_in, const int* in_sizes, int n_in,
                              void* d_out, int out_size) {
    const float* x      = (const float*)d_in[0];
    const float* weight = (const float*)d_in[1];
    const float* bias   = (const float*)d_in[2];
    const int*   neigh  = (const int*)d_in[3];
    float*       out    = (float*)d_out;

    cudaFuncSetAttribute(conv_kernel,
                         cudaFuncAttributeMaxDynamicSharedMemorySize,
                         SMEM_BYTES);

    transpose_kernel<<<NPIX / 32, 256>>>(x);
    conv_kernel<<<GRID, 256, SMEM_BYTES>>>(weight, bias, neigh, out);
}

// round 14
// speedup vs baseline: 2.3184x; 1.0214x over previous
#include <cuda_runtime.h>
#include <cuda_fp16.h>
#include <cstdint>

#define NSIDE 128
#define NPIX (12*NSIDE*NSIDE)   /* 196608 */
#define B 8
#define CIN 16
#define COUT 32
#define TILE_P 16
#define NT (NPIX/TILE_P)        /* 12288 */
#define GRID 296                /* persistent: 2 CTAs x 148 SMs */

#define ASTRIDE 304             /* bytes per A/B row (144 halves = 288B + 16 pad) */
#define A_BYTES (128*ASTRIDE)   /* 38912 per buffer */
#define A0_OFF 0
#define A1_OFF A_BYTES
#define B_OFF (2*A_BYTES)                 /* 77824 */
#define B_BYTES (32*ASTRIDE)              /* 9728 */
#define OS_OFF (B_OFF + B_BYTES)          /* 87552 */
#define OS_BYTES (256*17*4)               /* 17408 */
#define BS_OFF (OS_OFF + OS_BYTES)        /* 104960 */
#define SMEM_BYTES (BS_OFF + 128)         /* 105088; x2 = 210176 <= 228KB/SM */
#define OSTRIDE 17

// transposed fp16 x, pixel-major rows of [b*16+c], row NPIX = zeros
__device__ __align__(256) __half g_xh[(size_t)(NPIX + 1) * 128];

// ---------------------------------------------------------------------------
// Kernel A: transpose+convert x [B][CIN][NPIX] f32 -> g_xh [NPIX+1][b*16+c]
// ---------------------------------------------------------------------------
__global__ void transpose_kernel(const float* __restrict__ x) {
    __shared__ float tile[128 * 33];
    const int tid  = threadIdx.x;
    const int idx0 = blockIdx.x * 32;

    #pragma unroll
    for (int i = tid; i < 128 * 8; i += 256) {      // float4 loads
        int r  = i >> 3;
        int j4 = (i & 7) * 4;
        float4 v = *(const float4*)(x + r * NPIX + idx0 + j4);
        tile[r * 33 + j4 + 0] = v.x;
        tile[r * 33 + j4 + 1] = v.y;
        tile[r * 33 + j4 + 2] = v.z;
        tile[r * 33 + j4 + 3] = v.w;
    }
    __syncthreads();
    __half2* xh2 = (__half2*)g_xh;
    #pragma unroll
    for (int i = tid; i < 32 * 64; i += 256) {
        int j  = i >> 6;
        int cp = i & 63;
        __half2 h = __floats2half2_rn(tile[(2 * cp) * 33 + j],
                                      tile[(2 * cp + 1) * 33 + j]);
        xh2[(size_t)(idx0 + j) * 64 + cp] = h;
    }
    if (blockIdx.x == 0 && tid < 64)
        xh2[(size_t)NPIX * 64 + tid] = __floats2half2_rn(0.0f, 0.0f);
}

// ---------------------------------------------------------------------------
// PTX helpers (arch-agnostic under compute_103)
// ---------------------------------------------------------------------------
__device__ __forceinline__ void cp_async16(uint32_t dst_smem, const void* src) {
    asm volatile("cp.async.cg.shared.global [%0], [%1], 16;\n"
                 :: "r"(dst_smem), "l"(src));
}
__device__ __forceinline__ void ldsm_x4(uint32_t& r0, uint32_t& r1,
                                        uint32_t& r2, uint32_t& r3,
                                        uint32_t addr) {
    asm volatile("ldmatrix.sync.aligned.m8n8.x4.shared.b16 {%0,%1,%2,%3}, [%4];"
                 : "=r"(r0), "=r"(r1), "=r"(r2), "=r"(r3) : "r"(addr));
}
__device__ __forceinline__ void mma_16816(float& c0, float& c1, float& c2, float& c3,
                                          uint32_t a0, uint32_t a1, uint32_t a2, uint32_t a3,
                                          uint32_t b0, uint32_t b1) {
    asm volatile(
        "mma.sync.aligned.m16n8k16.row.col.f32.f16.f16.f32 "
        "{%0,%1,%2,%3}, {%4,%5,%6,%7}, {%8,%9}, {%0,%1,%2,%3};"
        : "+f"(c0), "+f"(c1), "+f"(c2), "+f"(c3)
        : "r"(a0), "r"(a1), "r"(a2), "r"(a3), "r"(b0), "r"(b1));
}

// ---------------------------------------------------------------------------
// Kernel B: persistent; each WARP gathers the 18 rows its own GEMM consumes
//   (per-warp cp.async groups, per-warp wait). Cross-warp coupling only at
//   the oS store phase, via one hard barrier + one slack arrive/wait barrier.
// ---------------------------------------------------------------------------
__global__ void __launch_bounds__(256, 2) conv_kernel(
    const float* __restrict__ weight,   // [COUT][CIN][9]
    const float* __restrict__ bias,     // [COUT]
    const int*   __restrict__ neigh,    // [NPIX][9]
    float*       __restrict__ out)      // [B][COUT][NPIX]
{
    extern __shared__ char smem[];
    const int tid  = threadIdx.x;
    const int wid  = tid >> 5;
    const int lane = tid & 31;

    uint32_t smem_u32;
    asm("{ .reg .u64 t; cvta.to.shared.u64 t, %1; cvt.u32.u64 %0, t; }"
        : "=r"(smem_u32) : "l"(smem));
    float* bS = (float*)(smem + BS_OFF);
    float* oS = (float*)(smem + OS_OFF);

    // ---- one-time prologue: weights [o][k] (k = kk*16+c), bias ----
    for (int i = tid; i < COUT * CIN * 9; i += 256) {
        int o = i / 144, rem = i - o * 144, c = rem / 9, kk = rem - c * 9;
        *(__half*)(smem + B_OFF + o * ASTRIDE + (kk * 16 + c) * 2) =
            __float2half_rn(weight[i]);
    }
    if (tid < 32) bS[tid] = bias[tid];

    // ---- per-lane gather constants (warp-local rows) ----
    // lane: pp = lane>>4 (which of the warp's 2 pixels), seg = lane&15
    // dst A row m = prow*8 + (seg>>1); byte offset kk*32 + (seg&1)*16
    const int pp   = lane >> 4;
    const int seg  = lane & 15;
    const int prow = 2 * wid + pp;             // pixel 0..15 in tile
    const uint32_t dBase = (uint32_t)((prow * 8 + (seg >> 1)) * ASTRIDE
                                      + (seg & 1) * 16);
    const char* xsrc = (const char*)g_xh + seg * 16;

    int nidx[9];
    auto prefetch = [&](int t_) {
        const int* np = neigh + (size_t)t_ * 144 + prow * 9;
        #pragma unroll
        for (int j = 0; j < 9; j++) nidx[j] = __ldg(np + j);
    };
    auto gather = [&](uint32_t abase) {
        #pragma unroll
        for (int j = 0; j < 9; j++)
            cp_async16(abase + dBase + j * 32, xsrc + (size_t)nidx[j] * 256);
        asm volatile("cp.async.commit_group;\n" ::: "memory");
    };

    // ldmatrix lane addresses (warp w reads rows 16w..16w+15 = its own gathers)
    const uint32_t aLane = (uint32_t)(wid * 16 + (lane & 15)) * ASTRIDE
                         + (lane >> 4) * 16;
    const uint32_t bAddr = smem_u32 + B_OFF
                         + (uint32_t)((lane >> 4) * 8 + (lane & 7)) * ASTRIDE
                         + ((lane >> 3) & 1) * 16;

    int t   = blockIdx.x;
    int cur = 0;

    prefetch(t);
    __syncthreads();                     // weights/bias staged (STS visibility)
    gather(smem_u32 + A0_OFF);           // own G(t) in flight
    if (t + GRID < NT) prefetch(t + GRID);
    asm volatile("bar.arrive 1, 512;" ::: "memory");   // prime slack barrier

    while (t < NT) {
        const int tn = t + GRID;

        if (tn < NT) {
            gather(smem_u32 + (cur ? A0_OFF : A1_OFF));   // own G(tn)
            asm volatile("cp.async.wait_group 1;\n" ::: "memory");  // own G(t)
        } else {
            asm volatile("cp.async.wait_group 0;\n" ::: "memory");
        }
        __syncwarp();                    // cross-lane visibility within warp

        if (tn + GRID < NT) prefetch(tn + GRID);

        // ---- GEMM on buffer cur (warp-local A slice) ----
        float acc[4][4];
        #pragma unroll
        for (int j = 0; j < 4; j++)
            #pragma unroll
            for (int i = 0; i < 4; i++) acc[j][i] = 0.0f;

        const uint32_t aAddr = smem_u32 + (cur ? A1_OFF : A0_OFF) + aLane;

        #pragma unroll
        for (int kk = 0; kk < 9; kk++) {
            uint32_t a0, a1, a2, a3, b0, b1, b2, b3, b4, b5, b6, b7;
            ldsm_x4(a0, a1, a2, a3, aAddr + kk * 32);
            ldsm_x4(b0, b1, b2, b3, bAddr + kk * 32);                 // o 0..15
            ldsm_x4(b4, b5, b6, b7, bAddr + 16 * ASTRIDE + kk * 32);  // o 16..31
            mma_16816(acc[0][0], acc[0][1], acc[0][2], acc[0][3], a0, a1, a2, a3, b0, b1);
            mma_16816(acc[1][0], acc[1][1], acc[1][2], acc[1][3], a0, a1, a2, a3, b2, b3);
            mma_16816(acc[2][0], acc[2][1], acc[2][2], acc[2][3], a0, a1, a2, a3, b4, b5);
            mma_16816(acc[3][0], acc[3][1], acc[3][2], acc[3][3], a0, a1, a2, a3, b6, b7);
        }

        // slack barrier: previous tile's stores must be done before re-staging
        asm volatile("bar.sync 1, 512;" ::: "memory");

        // ---- epilogue: frags -> oS (warp-exclusive columns 2w,2w+1) ----
        {
            const int g  = lane >> 2;       // = b
            const int tg = lane & 3;
            #pragma unroll
            for (int j = 0; j < 4; j++) {
                int o0 = j * 8 + tg * 2;
                float bi0 = bS[o0], bi1 = bS[o0 + 1];
                oS[(o0       * 8 + g) * OSTRIDE + wid * 2    ] = acc[j][0] + bi0;
                oS[((o0 + 1) * 8 + g) * OSTRIDE + wid * 2    ] = acc[j][1] + bi1;
                oS[(o0       * 8 + g) * OSTRIDE + wid * 2 + 1] = acc[j][2] + bi0;
                oS[((o0 + 1) * 8 + g) * OSTRIDE + wid * 2 + 1] = acc[j][3] + bi1;
            }
        }
        __syncthreads();                 // staging visible to all (hard)

        const int p0 = t * TILE_P;
        #pragma unroll
        for (int j = 0; j < 16; j++) {
            int i   = tid + j * 256;        // i = row*16 + p, row = b*32+o
            int row = i >> 4, p = i & 15;
            int b   = row >> 5, o = row & 31;
            out[row * NPIX + p0 + p] = oS[(o * 8 + b) * OSTRIDE + p];
        }
        asm volatile("bar.arrive 1, 512;" ::: "memory");   // stores(t) done

        t = tn;
        cur ^= 1;
    }
}

// ---------------------------------------------------------------------------
extern "C" void kernel_launch(void* const* d_in, const int* in_sizes, int n_in,
                              void* d_out, int out_size) {
    const float* x      = (const float*)d_in[0];
    const float* weight = (const float*)d_in[1];
    const float* bias   = (const float*)d_in[2];
    const int*   neigh  = (const int*)d_in[3];
    float*       out    = (float*)d_out;

    cudaFuncSetAttribute(conv_kernel,
                         cudaFuncAttributeMaxDynamicSharedMemorySize,
                         SMEM_BYTES);

    transpose_kernel<<<NPIX / 32, 256>>>(x);
    conv_kernel<<<GRID, 256, SMEM_BYTES>>>(weight, bias, neigh, out);
}